// round 17
// baseline (speedup 1.0000x reference)
#include <cuda_runtime.h>
#include <cuda_fp16.h>
#include <math.h>

#define T_LEN    8192
#define VOCAB    50257
#define NCHUNK   16               // 8192 = 16 * 512 exactly (no padding)
#define CHUNK    512
#define NQTILE   64               // 64 CTAs x 128 queries
#define NTHREADS 128

// scratch (device globals; no allocation allowed)
__device__ float4 g_qt[T_LEN];                 // tf32 bits of q' = QSCALE*(Wk^T Wq)p, w=0
__device__ float4 g_pt[T_LEN];                 // tf32 bits of (px,py,pz,1)
__device__ __half g_pBh[4][T_LEN];             // f16 hi of (px,py,pz,1), component-major
__device__ __half g_pBl[4][T_LEN];             // f16 lo (residual)
__device__ float  g_part[NCHUNK][T_LEN][4];    // per-chunk (Se*px, Se*py, Se*pz, Se)
__device__ unsigned g_cnt2[NQTILE];            // monotonic arrival counters (mod-16)

__device__ __forceinline__ unsigned f2tf32(float x) {
    unsigned r; asm("cvt.rna.tf32.f32 %0, %1;" : "=r"(r) : "f"(x)); return r;
}
__device__ __forceinline__ unsigned pack_h2(float lo, float hi) {
    unsigned r; asm("cvt.rn.f16x2.f32 %0, %1, %2;" : "=r"(r) : "f"(hi), "f"(lo)); return r;
}
__device__ __forceinline__ unsigned h2ex2(unsigned x) {
    unsigned r; asm("ex2.approx.f16x2 %0, %1;" : "=r"(r) : "r"(x)); return r;
}
// FMA-pipe exp2: magic-add range reduction (exact int part), deg-4 Taylor on
// [-0.5,0.5] (rel err ~2e-6 << f16 quantization), exponent re-attached via ALU.
__device__ __forceinline__ float exp2_poly(float s) {
    const float MAGIC = 12582912.0f;           // 1.5 * 2^23
    float t = s + MAGIC;
    float n = t - MAGIC;
    float f = s - n;
    float p = fmaf(f, 0.0096181291f, 0.0555041087f);
    p = fmaf(f, p, 0.2402265070f);
    p = fmaf(f, p, 0.6931471806f);
    p = fmaf(f, p, 1.0f);
    unsigned e = __float_as_uint(p) + (__float_as_uint(t) << 23);
    return __uint_as_float(e);
}
// two poly exps -> packed f16x2 (zero MUFU)
__device__ __forceinline__ unsigned e2h2_poly(float slo, float shi) {
    return pack_h2(exp2_poly(slo), exp2_poly(shi));
}
// S-MMA: m16n8k8 tf32, C = 0 (scores). k=4..7 zero-padded.
__device__ __forceinline__ void mma_tf32_z(float d[4], unsigned a0, unsigned a1, unsigned b0) {
    asm volatile(
        "mma.sync.aligned.m16n8k8.row.col.f32.tf32.tf32.f32 "
        "{%0,%1,%2,%3}, {%4,%5,%6,%7}, {%8,%9}, {%10,%11,%12,%13};"
        : "=f"(d[0]), "=f"(d[1]), "=f"(d[2]), "=f"(d[3])
        : "r"(a0), "r"(a1), "r"(0u), "r"(0u), "r"(b0), "r"(0u),
          "f"(0.0f), "f"(0.0f), "f"(0.0f), "f"(0.0f));
}
// accum MMA: m16n8k16 f16 inputs, f32 accumulators (C==D) — 16 keys per inst
__device__ __forceinline__ void mma_f16_k16(float c[4],
                                            unsigned a0, unsigned a1, unsigned a2, unsigned a3,
                                            unsigned b0, unsigned b1) {
    asm volatile(
        "mma.sync.aligned.m16n8k16.row.col.f32.f16.f16.f32 "
        "{%0,%1,%2,%3}, {%4,%5,%6,%7}, {%8,%9}, {%0,%1,%2,%3};"
        : "+f"(c[0]), "+f"(c[1]), "+f"(c[2]), "+f"(c[3])
        : "r"(a0), "r"(a1), "r"(a2), "r"(a3), "r"(b0), "r"(b1));
}

// fp32 Cody-Waite range reduction (n <= 328) + fast intrinsic trig.
__device__ __forceinline__ float red2pi(float x) {
    float n = rintf(x * 0.15915494309f);
    float r = fmaf(n, -6.28125f, x);
    return fmaf(n, -0.0019353072f, r);
}
__device__ __forceinline__ float cos_red(float x) { return __cosf(red2pi(x)); }
__device__ __forceinline__ float sin_red(float x) { return __sinf(red2pi(x)); }

// ---------------------------------------------------------------------------
// Kernel 1: gather + posenc; emit tf32 q', tf32 p, f16 hi/lo of p.
// ---------------------------------------------------------------------------
__global__ __launch_bounds__(64)
void prep_kernel(const int* __restrict__ x,
                 const float* __restrict__ emb,
                 const float* __restrict__ Wk,
                 const float* __restrict__ Wq) {
    int t = blockIdx.x * blockDim.x + threadIdx.x;
    if (t >= T_LEN) return;

    int xi = x[t];
    xi = min(max(xi, 0), VOCAB - 1);

    float a = 6.28f * (float)t;
    float p0 = emb[xi * 3 + 0] + cos_red(a / 25.0f);
    float p1 = emb[xi * 3 + 1] + sin_red(a / 25.0f);
    float p2 = emb[xi * 3 + 2] + sin_red(a / 5.0f);

    const float QSCALE = 0.8329465708f;  // log2(e)/sqrt(3)

    float q0 = 0.f, q1 = 0.f, q2 = 0.f;
    #pragma unroll
    for (int aa = 0; aa < 3; ++aa) {
        float qq = fmaf(Wq[aa * 3 + 0], p0,
                   fmaf(Wq[aa * 3 + 1], p1, Wq[aa * 3 + 2] * p2));
        q0 = fmaf(Wk[aa * 3 + 0], qq, q0);
        q1 = fmaf(Wk[aa * 3 + 1], qq, q1);
        q2 = fmaf(Wk[aa * 3 + 2], qq, q2);
    }
    g_qt[t] = make_float4(__uint_as_float(f2tf32(q0 * QSCALE)),
                          __uint_as_float(f2tf32(q1 * QSCALE)),
                          __uint_as_float(f2tf32(q2 * QSCALE)), 0.0f);
    g_pt[t] = make_float4(__uint_as_float(f2tf32(p0)),
                          __uint_as_float(f2tf32(p1)),
                          __uint_as_float(f2tf32(p2)), 1.0f);

    float pc[4] = {p0, p1, p2, 1.0f};
    #pragma unroll
    for (int c = 0; c < 4; ++c) {
        __half h = __float2half_rn(pc[c]);
        g_pBh[c][t] = h;
        g_pBl[c][t] = __float2half_rn(pc[c] - __half2float(h));
    }
}

// ---------------------------------------------------------------------------
// Kernel 2: attention, fully tensorized, exp split 4:4 MUFU:FMA-poly
// (dots + accumulation live on the tensor pipe, so FMA has headroom now).
// Tail: last-arriving chunk-CTA per qtile reduces its own 128 queries.
// ---------------------------------------------------------------------------
__global__ __launch_bounds__(NTHREADS, 7)
void attn_kernel(const float* __restrict__ Wv, float* __restrict__ out) {
    __shared__ float4 sPt[CHUNK];        // tf32 bits of p4
    __shared__ __half sBh[4][CHUNK];     // f16 hi, component-major
    __shared__ __half sBl[4][CHUNK];     // f16 lo
    __shared__ unsigned s_old;

    const int tid  = threadIdx.x;
    const int warp = tid >> 5;
    const int lane = tid & 31;
    const int g    = lane >> 2;
    const int tg   = lane & 3;
    const int kbeg = blockIdx.y * CHUNK;

    for (int i = tid; i < CHUNK; i += NTHREADS)
        sPt[i] = g_pt[kbeg + i];
    #pragma unroll
    for (int c = 0; c < 4; ++c) {
        const unsigned* gh = (const unsigned*)&g_pBh[c][kbeg];
        const unsigned* gl = (const unsigned*)&g_pBl[c][kbeg];
        unsigned* sh = (unsigned*)&sBh[c][0];
        unsigned* sl = (unsigned*)&sBl[c][0];
        for (int i = tid; i < CHUNK / 2; i += NTHREADS) {
            sh[i] = gh[i];
            sl[i] = gl[i];
        }
    }
    __syncthreads();

    const int qbase = blockIdx.x * 128 + warp * 32;
    const float* qtf = (const float*)g_qt;
    unsigned qa0 = __float_as_uint(qtf[(qbase + g     ) * 4 + tg]);
    unsigned qa1 = __float_as_uint(qtf[(qbase + g +  8) * 4 + tg]);
    unsigned qa2 = __float_as_uint(qtf[(qbase + g + 16) * 4 + tg]);
    unsigned qa3 = __float_as_uint(qtf[(qbase + g + 24) * 4 + tg]);

    float c0[4] = {0.f, 0.f, 0.f, 0.f};
    float c1[4] = {0.f, 0.f, 0.f, 0.f};

    const float* sPtf = (const float*)sPt;

    #pragma unroll 4
    for (int j = 0; j < CHUNK; j += 16) {
        unsigned b0a = __float_as_uint(sPtf[(j + g) * 4 + tg]);
        unsigned b0b = __float_as_uint(sPtf[(j + 8 + g) * 4 + tg]);

        float s0[4], s1[4], s2[4], s3[4];
        mma_tf32_z(s0, qa0, qa1, b0a);   // rows g,g+8    x keys j..j+7
        mma_tf32_z(s1, qa2, qa3, b0a);   // rows g+16,+24 x keys j..j+7
        mma_tf32_z(s2, qa0, qa1, b0b);   // rows g,g+8    x keys j+8..j+15
        mma_tf32_z(s3, qa2, qa3, b0b);   // rows g+16,+24 x keys j+8..j+15

        // exp fragments: c0 tile via MUFU f16x2, c1 tile via FMA-pipe poly
        unsigned a0 = h2ex2(pack_h2(s0[0], s0[1]));
        unsigned a1 = h2ex2(pack_h2(s0[2], s0[3]));
        unsigned a2 = h2ex2(pack_h2(s2[0], s2[1]));
        unsigned a3 = h2ex2(pack_h2(s2[2], s2[3]));
        unsigned a4 = e2h2_poly(s1[0], s1[1]);
        unsigned a5 = e2h2_poly(s1[2], s1[3]);
        unsigned a6 = e2h2_poly(s3[0], s3[1]);
        unsigned a7 = e2h2_poly(s3[2], s3[3]);

        unsigned bh0 = 0u, bh1 = 0u, bl0 = 0u, bl1 = 0u;
        if (g < 4) {
            bh0 = *(const unsigned*)&sBh[g][j + 2 * tg];
            bh1 = *(const unsigned*)&sBh[g][j + 8 + 2 * tg];
            bl0 = *(const unsigned*)&sBl[g][j + 2 * tg];
            bl1 = *(const unsigned*)&sBl[g][j + 8 + 2 * tg];
        }

        mma_f16_k16(c0, a0, a1, a2, a3, bh0, bh1);
        mma_f16_k16(c0, a0, a1, a2, a3, bl0, bl1);
        mma_f16_k16(c1, a4, a5, a6, a7, bh0, bh1);
        mma_f16_k16(c1, a4, a5, a6, a7, bl0, bl1);
    }

    if (tg < 2) {
        const int cc = blockIdx.y;
        float2* o;
        o = (float2*)&g_part[cc][qbase + g     ][2 * tg]; *o = make_float2(c0[0], c0[1]);
        o = (float2*)&g_part[cc][qbase + g +  8][2 * tg]; *o = make_float2(c0[2], c0[3]);
        o = (float2*)&g_part[cc][qbase + g + 16][2 * tg]; *o = make_float2(c1[0], c1[1]);
        o = (float2*)&g_part[cc][qbase + g + 24][2 * tg]; *o = make_float2(c1[2], c1[3]);
    }

    // ---- fused tail reduce: last-arriving chunk-CTA per qtile ----
    __threadfence();
    __syncthreads();
    if (tid == 0)
        s_old = atomicAdd(&g_cnt2[blockIdx.x], 1u);
    __syncthreads();

    if (s_old % NCHUNK == NCHUNK - 1) {
        int qq = blockIdx.x * 128 + tid;
        float r0 = 0.f, r1 = 0.f, r2 = 0.f, rd = 0.f;
        #pragma unroll
        for (int s = 0; s < NCHUNK; ++s) {
            float4 p = *(const float4*)&g_part[s][qq][0];
            r0 += p.x; r1 += p.y; r2 += p.z; rd += p.w;
        }
        float inv = 1.0f / rd;
        out[qq * 3 + 0] = fmaf(Wv[0], r0, fmaf(Wv[1], r1, Wv[2] * r2)) * inv;
        out[qq * 3 + 1] = fmaf(Wv[3], r0, fmaf(Wv[4], r1, Wv[5] * r2)) * inv;
        out[qq * 3 + 2] = fmaf(Wv[6], r0, fmaf(Wv[7], r1, Wv[8] * r2)) * inv;
    }
}

extern "C" void kernel_launch(void* const* d_in, const int* in_sizes, int n_in,
                              void* d_out, int out_size) {
    const int*   x   = (const int*)  d_in[0];
    const float* emb = (const float*)d_in[1];
    const float* Wk  = (const float*)d_in[2];
    const float* Wq  = (const float*)d_in[3];
    const float* Wv  = (const float*)d_in[4];
    float* out = (float*)d_out;

    prep_kernel<<<T_LEN / 64, 64>>>(x, emb, Wk, Wq);
    attn_kernel<<<dim3(NQTILE, NCHUNK), NTHREADS>>>(Wv, out);
}